// round 1
// baseline (speedup 1.0000x reference)
#include <cuda_runtime.h>
#include <math.h>

#define NN 100000
#define DD 16
#define HH 128
#define CC 10

// Scratch (no allocations allowed) — ~205 MB total
__device__ float g_hA[NN*HH];    // layer-0 output h
__device__ float g_hs0[NN*HH];   // LSTM hidden state ping
__device__ float g_hs1[NN*HH];   // LSTM hidden state pong
__device__ float g_cs[NN*HH];    // LSTM cell state (in-place safe)

__device__ __forceinline__ float sigf(float x) { return 1.f / (1.f + expf(-x)); }

// ---------------------------------------------------------------------------
// Fused LSTM step: gates[64 nodes][4 gates x 32 hidden] = [x|hs] @ [Wih|Whh]^T
// then bias + sigmoid/tanh + state update, all in one block.
// Block = 64 nodes x 32 hidden units (=> 128 gate columns). 256 threads,
// 4x8 microtile per thread, K=256 in chunks of 16.
// ---------------------------------------------------------------------------
__global__ __launch_bounds__(256) void lstm_step_kernel(
    const float* __restrict__ h_in, const int* __restrict__ nbr, int step,
    const float* __restrict__ hs_in, float* __restrict__ hs_out,
    float* __restrict__ cs,
    const float* __restrict__ Wih, const float* __restrict__ Whh,
    const float* __restrict__ bias, int first)
{
    __shared__ __align__(16) union {
        struct { float As[16][68]; float Bs[16][132]; } s;
        float g[64][128];
    } sm;
    __shared__ int nidx[64];

    const int tid = threadIdx.x;
    const int tx = tid & 15, ty = tid >> 4;
    const int m0 = blockIdx.x * 64;
    const int j0 = blockIdx.y * 32;

    if (tid < 64) {
        int m = m0 + tid;
        nidx[tid] = (m < NN) ? nbr[m * DD + step] : 0;
    }
    __syncthreads();

    float acc[4][8];
#pragma unroll
    for (int r = 0; r < 4; r++)
#pragma unroll
        for (int c = 0; c < 8; c++) acc[r][c] = 0.f;

    for (int kk = 0; kk < 256; kk += 16) {
        // A tile: [x | hs], 64 rows x 16 k, coalesced (16 threads per row)
#pragma unroll
        for (int i = 0; i < 4; i++) {
            int idx = tid + i * 256;
            int m = idx >> 4, kl = idx & 15;
            int k = kk + kl;
            int mg = m0 + m;
            float v = 0.f;
            if (mg < NN) {
                if (k < HH) v = h_in[nidx[m] * HH + k];
                else if (!first) v = hs_in[mg * HH + (k - HH)];
            }
            sm.s.As[kl][m] = v;
        }
        // B tile: weight rows r = gate*128 + j0 + jl, 128 cols x 16 k
#pragma unroll
        for (int i = 0; i < 8; i++) {
            int idx = tid + i * 256;
            int c = idx >> 4, kl = idx & 15;
            int k = kk + kl;
            int r = ((c >> 5) << 7) + j0 + (c & 31);
            float w = (k < HH) ? Wih[r * HH + k] : Whh[r * HH + (k - HH)];
            sm.s.Bs[kl][c] = w;
        }
        __syncthreads();
#pragma unroll
        for (int kl = 0; kl < 16; kl++) {
            float4 a  = *(const float4*)&sm.s.As[kl][ty * 4];
            float4 b0 = *(const float4*)&sm.s.Bs[kl][tx * 8];
            float4 b1 = *(const float4*)&sm.s.Bs[kl][tx * 8 + 4];
            float av[4] = {a.x, a.y, a.z, a.w};
            float bv[8] = {b0.x, b0.y, b0.z, b0.w, b1.x, b1.y, b1.z, b1.w};
#pragma unroll
            for (int r = 0; r < 4; r++)
#pragma unroll
                for (int c = 0; c < 8; c++)
                    acc[r][c] = fmaf(av[r], bv[c], acc[r][c]);
        }
        __syncthreads();
    }

    // Stage gates in smem so each thread can read its i/f/g/o quadruple
#pragma unroll
    for (int r = 0; r < 4; r++) {
        *(float4*)&sm.g[ty * 4 + r][tx * 8]     = make_float4(acc[r][0], acc[r][1], acc[r][2], acc[r][3]);
        *(float4*)&sm.g[ty * 4 + r][tx * 8 + 4] = make_float4(acc[r][4], acc[r][5], acc[r][6], acc[r][7]);
    }
    __syncthreads();

#pragma unroll
    for (int i = 0; i < 8; i++) {
        int idx = tid + i * 256;   // 64 nodes x 32 hidden = 2048
        int m = idx >> 5, j = idx & 31;
        int mg = m0 + m;
        if (mg < NN) {
            int jg = j0 + j;
            float gi = sm.g[m][j]      + bias[jg];
            float gf = sm.g[m][32 + j] + bias[HH + jg];
            float gg = sm.g[m][64 + j] + bias[2 * HH + jg];
            float go = sm.g[m][96 + j] + bias[3 * HH + jg];
            float cold = first ? 0.f : cs[mg * HH + jg];
            float cnew = sigf(gf) * cold + sigf(gi) * tanhf(gg);
            float hnew = sigf(go) * tanhf(cnew);
            cs[mg * HH + jg] = cnew;
            hs_out[mg * HH + jg] = hnew;
        }
    }
}

// ---------------------------------------------------------------------------
// Generic [N,128] = act( A1@W1^T (+ A2@W2^T) + b1 (+ b2) ), ktot in {128,256}
// Same 64x128 tile, 4x8 microtile. Used for SAGE combine + MLP layers.
// ---------------------------------------------------------------------------
__global__ __launch_bounds__(256) void gemm_kernel(
    const float* __restrict__ A1, const float* __restrict__ A2,
    const float* __restrict__ W1, const float* __restrict__ W2,
    const float* __restrict__ b1, const float* __restrict__ b2,
    float* __restrict__ out, int ktot, int relu)
{
    __shared__ __align__(16) float As[16][68];
    __shared__ __align__(16) float Bs[16][132];

    const int tid = threadIdx.x;
    const int tx = tid & 15, ty = tid >> 4;
    const int m0 = blockIdx.x * 64;

    float acc[4][8];
#pragma unroll
    for (int r = 0; r < 4; r++)
#pragma unroll
        for (int c = 0; c < 8; c++) acc[r][c] = 0.f;

    for (int kk = 0; kk < ktot; kk += 16) {
#pragma unroll
        for (int i = 0; i < 4; i++) {
            int idx = tid + i * 256;
            int m = idx >> 4, kl = idx & 15;
            int k = kk + kl;
            int mg = m0 + m;
            float v = 0.f;
            if (mg < NN)
                v = (k < HH) ? A1[mg * HH + k] : A2[mg * HH + (k - HH)];
            As[kl][m] = v;
        }
#pragma unroll
        for (int i = 0; i < 8; i++) {
            int idx = tid + i * 256;
            int c = idx >> 4, kl = idx & 15;
            int k = kk + kl;
            float w = (k < HH) ? W1[c * HH + k] : W2[c * HH + (k - HH)];
            Bs[kl][c] = w;
        }
        __syncthreads();
#pragma unroll
        for (int kl = 0; kl < 16; kl++) {
            float4 a  = *(const float4*)&As[kl][ty * 4];
            float4 b0v = *(const float4*)&Bs[kl][tx * 8];
            float4 b1v = *(const float4*)&Bs[kl][tx * 8 + 4];
            float av[4] = {a.x, a.y, a.z, a.w};
            float bv[8] = {b0v.x, b0v.y, b0v.z, b0v.w, b1v.x, b1v.y, b1v.z, b1v.w};
#pragma unroll
            for (int r = 0; r < 4; r++)
#pragma unroll
                for (int c = 0; c < 8; c++)
                    acc[r][c] = fmaf(av[r], bv[c], acc[r][c]);
        }
        __syncthreads();
    }

#pragma unroll
    for (int r = 0; r < 4; r++) {
        int mg = m0 + ty * 4 + r;
        if (mg < NN) {
#pragma unroll
            for (int c = 0; c < 8; c++) {
                int n = tx * 8 + c;
                float v = acc[r][c] + b1[n] + (b2 ? b2[n] : 0.f);
                if (relu) v = fmaxf(v, 0.f);
                acc[r][c] = v;
            }
            *(float4*)&out[mg * HH + tx * 8]     = make_float4(acc[r][0], acc[r][1], acc[r][2], acc[r][3]);
            *(float4*)&out[mg * HH + tx * 8 + 4] = make_float4(acc[r][4], acc[r][5], acc[r][6], acc[r][7]);
        }
    }
}

// ---------------------------------------------------------------------------
// Narrow head: out[N,nout] = x @ oW^T + ob  (nout = 10 or 1)
// ---------------------------------------------------------------------------
__global__ __launch_bounds__(256) void head_kernel(
    const float* __restrict__ x, const float* __restrict__ W,
    const float* __restrict__ b, float* __restrict__ out, int nout)
{
    __shared__ float xs[64][129];
    __shared__ float ws[CC * HH];
    const int tid = threadIdx.x;
    const int m0 = blockIdx.x * 64;

    for (int i = tid; i < nout * HH; i += 256) ws[i] = W[i];
    for (int i = tid; i < 64 * HH; i += 256) {
        int m = i >> 7, k = i & 127;
        int mg = m0 + m;
        xs[m][k] = (mg < NN) ? x[mg * HH + k] : 0.f;
    }
    __syncthreads();

    for (int idx = tid; idx < 64 * nout; idx += 256) {
        int m = idx / nout, c = idx % nout;
        int mg = m0 + m;
        if (mg < NN) {
            float acc = b[c];
#pragma unroll 4
            for (int k = 0; k < HH; k++)
                acc = fmaf(xs[m][k], ws[c * HH + k], acc);
            out[mg * nout + c] = acc;
        }
    }
}

// ---------------------------------------------------------------------------
extern "C" void kernel_launch(void* const* d_in, const int* in_sizes, int n_in,
                              void* d_out, int out_size)
{
    const float* h0    = (const float*)d_in[0];
    const int*   nbr   = (const int*)d_in[1];
    const float* Wih   = (const float*)d_in[2];
    const float* Whh   = (const float*)d_in[3];
    const float* lb    = (const float*)d_in[4];
    const float* Wsf   = (const float*)d_in[5];
    const float* bsf   = (const float*)d_in[6];
    const float* Wng   = (const float*)d_in[7];
    const float* bng   = (const float*)d_in[8];
    const float* clsW  = (const float*)d_in[9];
    const float* clsb  = (const float*)d_in[10];
    const float* clsoW = (const float*)d_in[11];
    const float* clsob = (const float*)d_in[12];
    const float* cnfW  = (const float*)d_in[13];
    const float* cnfb  = (const float*)d_in[14];
    const float* cnfoW = (const float*)d_in[15];
    const float* cnfob = (const float*)d_in[16];

    float* out   = (float*)d_out;
    float* out_o = out;                                   // [N, C]
    float* out_h = out + (size_t)NN * CC;                 // [N, H]
    float* out_l = out + (size_t)NN * CC + (size_t)NN * HH; // [N, 1]

    float *hA, *hs0, *hs1, *cs;
    cudaGetSymbolAddress((void**)&hA,  g_hA);
    cudaGetSymbolAddress((void**)&hs0, g_hs0);
    cudaGetSymbolAddress((void**)&hs1, g_hs1);
    cudaGetSymbolAddress((void**)&cs,  g_cs);

    const int MB = (NN + 63) / 64;  // 1563
    dim3 gL(MB, 4);                 // 4 hidden-unit tiles of 32
    dim3 gG(MB, 1);

    const float* hin = h0;
    float* hout_arr[2] = {hA, out_h};

    for (int layer = 0; layer < 2; layer++) {
        const float* Wih_l = Wih + (size_t)layer * 4 * HH * HH;
        const float* Whh_l = Whh + (size_t)layer * 4 * HH * HH;
        const float* lb_l  = lb + (size_t)layer * 4 * HH;
        float* hr = hs0;
        float* hw = hs1;
        for (int t = 0; t < DD; t++) {
            lstm_step_kernel<<<gL, 256>>>(hin, nbr, t, hr, hw, cs,
                                          Wih_l, Whh_l, lb_l, t == 0);
            float* tmp = hr; hr = hw; hw = tmp;   // hr now holds latest hs
        }
        // combine: relu(h @ Wself^T + bself + hs @ Wneigh^T + bneigh)
        gemm_kernel<<<gG, 256>>>(hin, hr,
                                 Wsf + (size_t)layer * HH * HH,
                                 Wng + (size_t)layer * HH * HH,
                                 bsf + (size_t)layer * HH,
                                 bng + (size_t)layer * HH,
                                 hout_arr[layer], 256, 1);
        hin = hout_arr[layer];
    }

    // cls head: 5x relu(Linear) + Linear(H->10)
    const float* x = out_h;
    float* pp[2] = {hs0, hs1};
    for (int i = 0; i < 5; i++) {
        gemm_kernel<<<gG, 256>>>(x, nullptr,
                                 clsW + (size_t)i * HH * HH, nullptr,
                                 clsb + (size_t)i * HH, nullptr,
                                 pp[i & 1], 128, 1);
        x = pp[i & 1];
    }
    head_kernel<<<MB, 256>>>(x, clsoW, clsob, out_o, CC);

    // cnf head: 5x relu(Linear) + Linear(H->1)
    x = out_h;
    for (int i = 0; i < 5; i++) {
        gemm_kernel<<<gG, 256>>>(x, nullptr,
                                 cnfW + (size_t)i * HH * HH, nullptr,
                                 cnfb + (size_t)i * HH, nullptr,
                                 pp[i & 1], 128, 1);
        x = pp[i & 1];
    }
    head_kernel<<<MB, 256>>>(x, cnfoW, cnfob, out_l, 1);
}

// round 2
// speedup vs baseline: 2.2656x; 2.2656x over previous
#include <cuda_runtime.h>
#include <math.h>

#define NN 100000
#define DD 16
#define HH 128
#define CC 10

#define MT 128   // nodes per block
#define KT 16    // k-chunk
#define PAD 132  // smem row pad

// Scratch (no allocations allowed)
__device__ float g_hA[NN*HH];    // layer-0 output h
__device__ float g_hs0[NN*HH];   // LSTM hidden state ping
__device__ float g_hs1[NN*HH];   // LSTM hidden state pong
__device__ float g_cs[NN*HH];    // LSTM cell state (in-place safe)

__device__ __forceinline__ float sigf(float x) {
    return __fdividef(1.f, 1.f + __expf(-x));
}
__device__ __forceinline__ float tanh_(float x) {
    float e = __expf(2.f * x);
    return 1.f - __fdividef(2.f, e + 1.f);
}

// ---------------------------------------------------------------------------
// Fused LSTM step. Block = 128 nodes x 32 hidden units (128 gate columns,
// gate-interleaved: col c = j_local*4 + gate). 256 threads, 8x8 microtile,
// K=256 in 16 chunks of 16, register->smem double buffering (1 sync/chunk).
// Epilogue (bias + sigmoid/tanh + state update) entirely in registers.
// ---------------------------------------------------------------------------
__global__ __launch_bounds__(256, 2) void lstm_step_kernel(
    const float* __restrict__ h_in, const int* __restrict__ nbr, int step,
    const float* __restrict__ hs_in, float* __restrict__ hs_out,
    float* __restrict__ cs,
    const float* __restrict__ Wih, const float* __restrict__ Whh,
    const float* __restrict__ bias, int first)
{
    __shared__ __align__(16) float As[2][KT][PAD];
    __shared__ __align__(16) float Bs[2][KT][PAD];
    __shared__ int nidx[MT];

    const int tid = threadIdx.x;
    const int tx = tid & 15, ty = tid >> 4;
    const int m0 = blockIdx.x * MT;
    const int j0 = blockIdx.y * 32;

    if (tid < MT) {
        int m = m0 + tid;
        nidx[tid] = (m < NN) ? nbr[m * DD + step] : 0;
    }
    __syncthreads();

    // per-thread load slots: A: idx4 = tid + i*256 -> m = idx4>>2, k4 = idx4&3
    //                        B: same mapping -> c = idx4>>2
    int a_m[2], a_k4[2], b_c[2], b_k4[2], b_r[2];
#pragma unroll
    for (int i = 0; i < 2; i++) {
        int idx4 = tid + i * 256;
        a_m[i] = idx4 >> 2;  a_k4[i] = idx4 & 3;
        b_c[i] = idx4 >> 2;  b_k4[i] = idx4 & 3;
        int c = b_c[i];
        b_r[i] = (c & 3) * HH + j0 + (c >> 2);   // gate*128 + j0 + j
    }

    float4 ra[2], rb[2];

    // prologue: fetch chunk 0 (k in [0,16): x-part only)
#pragma unroll
    for (int i = 0; i < 2; i++) {
        ra[i] = *(const float4*)(h_in + (size_t)nidx[a_m[i]] * HH + a_k4[i] * 4);
        rb[i] = *(const float4*)(Wih + (size_t)b_r[i] * HH + b_k4[i] * 4);
    }
#pragma unroll
    for (int i = 0; i < 2; i++) {
        float* pa = &As[0][a_k4[i] * 4][a_m[i]];
        pa[0*PAD] = ra[i].x; pa[1*PAD] = ra[i].y; pa[2*PAD] = ra[i].z; pa[3*PAD] = ra[i].w;
        float* pb = &Bs[0][b_k4[i] * 4][b_c[i]];
        pb[0*PAD] = rb[i].x; pb[1*PAD] = rb[i].y; pb[2*PAD] = rb[i].z; pb[3*PAD] = rb[i].w;
    }
    __syncthreads();

    float acc[8][8];
#pragma unroll
    for (int r = 0; r < 8; r++)
#pragma unroll
        for (int c = 0; c < 8; c++) acc[r][c] = 0.f;

    int p = 0;
    for (int it = 0; it < 16; it++) {
        int kn = (it + 1) * KT;
        if (it < 15) {
            // prefetch next chunk into registers
#pragma unroll
            for (int i = 0; i < 2; i++) {
                int k = kn + a_k4[i] * 4;
                if (k < HH) {
                    ra[i] = *(const float4*)(h_in + (size_t)nidx[a_m[i]] * HH + k);
                } else {
                    int mg = m0 + a_m[i];
                    if (!first && mg < NN)
                        ra[i] = *(const float4*)(hs_in + (size_t)mg * HH + (k - HH));
                    else
                        ra[i] = make_float4(0.f, 0.f, 0.f, 0.f);
                }
                int kb = kn + b_k4[i] * 4;
                rb[i] = (kb < HH)
                    ? *(const float4*)(Wih + (size_t)b_r[i] * HH + kb)
                    : *(const float4*)(Whh + (size_t)b_r[i] * HH + (kb - HH));
            }
        }
        // compute on buffer p
#pragma unroll
        for (int kl = 0; kl < KT; kl++) {
            float4 a0 = *(const float4*)&As[p][kl][ty * 8];
            float4 a1 = *(const float4*)&As[p][kl][ty * 8 + 4];
            float4 b0 = *(const float4*)&Bs[p][kl][tx * 8];
            float4 b1 = *(const float4*)&Bs[p][kl][tx * 8 + 4];
            float av[8] = {a0.x, a0.y, a0.z, a0.w, a1.x, a1.y, a1.z, a1.w};
            float bv[8] = {b0.x, b0.y, b0.z, b0.w, b1.x, b1.y, b1.z, b1.w};
#pragma unroll
            for (int r = 0; r < 8; r++)
#pragma unroll
                for (int c = 0; c < 8; c++)
                    acc[r][c] = fmaf(av[r], bv[c], acc[r][c]);
        }
        if (it < 15) {
            int q = p ^ 1;
#pragma unroll
            for (int i = 0; i < 2; i++) {
                float* pa = &As[q][a_k4[i] * 4][a_m[i]];
                pa[0*PAD] = ra[i].x; pa[1*PAD] = ra[i].y; pa[2*PAD] = ra[i].z; pa[3*PAD] = ra[i].w;
                float* pb = &Bs[q][b_k4[i] * 4][b_c[i]];
                pb[0*PAD] = rb[i].x; pb[1*PAD] = rb[i].y; pb[2*PAD] = rb[i].z; pb[3*PAD] = rb[i].w;
            }
            __syncthreads();
            p = q;
        }
    }

    // Epilogue: thread owns m = m0+ty*8+r (r=0..7), j pair jg = j0+tx*2+{0,1}.
    // acc[r][jj*4 + gate] = gate value for (m, jg+jj), gate order i,f,g,o.
    const int jl = tx * 2;
    float bI[2], bF[2], bG[2], bO[2];
#pragma unroll
    for (int jj = 0; jj < 2; jj++) {
        int jg = j0 + jl + jj;
        bI[jj] = bias[jg];
        bF[jj] = bias[HH + jg];
        bG[jj] = bias[2 * HH + jg];
        bO[jj] = bias[3 * HH + jg];
    }
#pragma unroll
    for (int r = 0; r < 8; r++) {
        int mg = m0 + ty * 8 + r;
        if (mg < NN) {
            float2 cold = first ? make_float2(0.f, 0.f)
                                : *(const float2*)(cs + (size_t)mg * HH + j0 + jl);
            float coldv[2] = {cold.x, cold.y};
            float cnv[2], hnv[2];
#pragma unroll
            for (int jj = 0; jj < 2; jj++) {
                float gi = acc[r][jj * 4 + 0] + bI[jj];
                float gf = acc[r][jj * 4 + 1] + bF[jj];
                float gg = acc[r][jj * 4 + 2] + bG[jj];
                float go = acc[r][jj * 4 + 3] + bO[jj];
                float cn = sigf(gf) * coldv[jj] + sigf(gi) * tanh_(gg);
                cnv[jj] = cn;
                hnv[jj] = sigf(go) * tanh_(cn);
            }
            *(float2*)(cs + (size_t)mg * HH + j0 + jl)     = make_float2(cnv[0], cnv[1]);
            *(float2*)(hs_out + (size_t)mg * HH + j0 + jl) = make_float2(hnv[0], hnv[1]);
        }
    }
}

// ---------------------------------------------------------------------------
// Generic [N,128] = act( A1@W1^T (+ A2@W2^T) + b1 (+ b2) ), ktot in {128,256}
// ---------------------------------------------------------------------------
__global__ __launch_bounds__(256) void gemm_kernel(
    const float* __restrict__ A1, const float* __restrict__ A2,
    const float* __restrict__ W1, const float* __restrict__ W2,
    const float* __restrict__ b1, const float* __restrict__ b2,
    float* __restrict__ out, int ktot, int relu)
{
    __shared__ __align__(16) float As[16][68];
    __shared__ __align__(16) float Bs[16][132];

    const int tid = threadIdx.x;
    const int tx = tid & 15, ty = tid >> 4;
    const int m0 = blockIdx.x * 64;

    float acc[4][8];
#pragma unroll
    for (int r = 0; r < 4; r++)
#pragma unroll
        for (int c = 0; c < 8; c++) acc[r][c] = 0.f;

    for (int kk = 0; kk < ktot; kk += 16) {
#pragma unroll
        for (int i = 0; i < 4; i++) {
            int idx = tid + i * 256;
            int m = idx >> 4, kl = idx & 15;
            int k = kk + kl;
            int mg = m0 + m;
            float v = 0.f;
            if (mg < NN)
                v = (k < HH) ? A1[(size_t)mg * HH + k] : A2[(size_t)mg * HH + (k - HH)];
            As[kl][m] = v;
        }
#pragma unroll
        for (int i = 0; i < 8; i++) {
            int idx = tid + i * 256;
            int c = idx >> 4, kl = idx & 15;
            int k = kk + kl;
            float w = (k < HH) ? W1[(size_t)c * HH + k] : W2[(size_t)c * HH + (k - HH)];
            Bs[kl][c] = w;
        }
        __syncthreads();
#pragma unroll
        for (int kl = 0; kl < 16; kl++) {
            float4 a  = *(const float4*)&As[kl][ty * 4];
            float4 b0v = *(const float4*)&Bs[kl][tx * 8];
            float4 b1v = *(const float4*)&Bs[kl][tx * 8 + 4];
            float av[4] = {a.x, a.y, a.z, a.w};
            float bv[8] = {b0v.x, b0v.y, b0v.z, b0v.w, b1v.x, b1v.y, b1v.z, b1v.w};
#pragma unroll
            for (int r = 0; r < 4; r++)
#pragma unroll
                for (int c = 0; c < 8; c++)
                    acc[r][c] = fmaf(av[r], bv[c], acc[r][c]);
        }
        __syncthreads();
    }

#pragma unroll
    for (int r = 0; r < 4; r++) {
        int mg = m0 + ty * 4 + r;
        if (mg < NN) {
#pragma unroll
            for (int c = 0; c < 8; c++) {
                int n = tx * 8 + c;
                float v = acc[r][c] + b1[n] + (b2 ? b2[n] : 0.f);
                if (relu) v = fmaxf(v, 0.f);
                acc[r][c] = v;
            }
            *(float4*)&out[(size_t)mg * HH + tx * 8]     = make_float4(acc[r][0], acc[r][1], acc[r][2], acc[r][3]);
            *(float4*)&out[(size_t)mg * HH + tx * 8 + 4] = make_float4(acc[r][4], acc[r][5], acc[r][6], acc[r][7]);
        }
    }
}

// ---------------------------------------------------------------------------
// Narrow head: out[N,nout] = x @ oW^T + ob  (nout = 10 or 1)
// ---------------------------------------------------------------------------
__global__ __launch_bounds__(256) void head_kernel(
    const float* __restrict__ x, const float* __restrict__ W,
    const float* __restrict__ b, float* __restrict__ out, int nout)
{
    __shared__ float xs[64][129];
    __shared__ float ws[CC * HH];
    const int tid = threadIdx.x;
    const int m0 = blockIdx.x * 64;

    for (int i = tid; i < nout * HH; i += 256) ws[i] = W[i];
    for (int i = tid; i < 64 * HH; i += 256) {
        int m = i >> 7, k = i & 127;
        int mg = m0 + m;
        xs[m][k] = (mg < NN) ? x[(size_t)mg * HH + k] : 0.f;
    }
    __syncthreads();

    for (int idx = tid; idx < 64 * nout; idx += 256) {
        int m = idx / nout, c = idx % nout;
        int mg = m0 + m;
        if (mg < NN) {
            float acc = b[c];
#pragma unroll 4
            for (int k = 0; k < HH; k++)
                acc = fmaf(xs[m][k], ws[c * HH + k], acc);
            out[(size_t)mg * nout + c] = acc;
        }
    }
}

// ---------------------------------------------------------------------------
extern "C" void kernel_launch(void* const* d_in, const int* in_sizes, int n_in,
                              void* d_out, int out_size)
{
    const float* h0    = (const float*)d_in[0];
    const int*   nbr   = (const int*)d_in[1];
    const float* Wih   = (const float*)d_in[2];
    const float* Whh   = (const float*)d_in[3];
    const float* lb    = (const float*)d_in[4];
    const float* Wsf   = (const float*)d_in[5];
    const float* bsf   = (const float*)d_in[6];
    const float* Wng   = (const float*)d_in[7];
    const float* bng   = (const float*)d_in[8];
    const float* clsW  = (const float*)d_in[9];
    const float* clsb  = (const float*)d_in[10];
    const float* clsoW = (const float*)d_in[11];
    const float* clsob = (const float*)d_in[12];
    const float* cnfW  = (const float*)d_in[13];
    const float* cnfb  = (const float*)d_in[14];
    const float* cnfoW = (const float*)d_in[15];
    const float* cnfob = (const float*)d_in[16];

    float* out   = (float*)d_out;
    float* out_o = out;                                     // [N, C]
    float* out_h = out + (size_t)NN * CC;                   // [N, H]
    float* out_l = out + (size_t)NN * CC + (size_t)NN * HH; // [N, 1]

    float *hA, *hs0, *hs1, *cs;
    cudaGetSymbolAddress((void**)&hA,  g_hA);
    cudaGetSymbolAddress((void**)&hs0, g_hs0);
    cudaGetSymbolAddress((void**)&hs1, g_hs1);
    cudaGetSymbolAddress((void**)&cs,  g_cs);

    const int MBL = (NN + MT - 1) / MT;   // 782 (lstm)
    const int MB  = (NN + 63) / 64;       // 1563 (gemm/head)
    dim3 gL(MBL, 4);
    dim3 gG(MB, 1);

    const float* hin = h0;
    float* hout_arr[2] = {hA, out_h};

    for (int layer = 0; layer < 2; layer++) {
        const float* Wih_l = Wih + (size_t)layer * 4 * HH * HH;
        const float* Whh_l = Whh + (size_t)layer * 4 * HH * HH;
        const float* lb_l  = lb + (size_t)layer * 4 * HH;
        float* hr = hs0;
        float* hw = hs1;
        for (int t = 0; t < DD; t++) {
            lstm_step_kernel<<<gL, 256>>>(hin, nbr, t, hr, hw, cs,
                                          Wih_l, Whh_l, lb_l, t == 0);
            float* tmp = hr; hr = hw; hw = tmp;   // hr now holds latest hs
        }
        gemm_kernel<<<gG, 256>>>(hin, hr,
                                 Wsf + (size_t)layer * HH * HH,
                                 Wng + (size_t)layer * HH * HH,
                                 bsf + (size_t)layer * HH,
                                 bng + (size_t)layer * HH,
                                 hout_arr[layer], 256, 1);
        hin = hout_arr[layer];
    }

    const float* x = out_h;
    float* pp[2] = {hs0, hs1};
    for (int i = 0; i < 5; i++) {
        gemm_kernel<<<gG, 256>>>(x, nullptr,
                                 clsW + (size_t)i * HH * HH, nullptr,
                                 clsb + (size_t)i * HH, nullptr,
                                 pp[i & 1], 128, 1);
        x = pp[i & 1];
    }
    head_kernel<<<MB, 256>>>(x, clsoW, clsob, out_o, CC);

    x = out_h;
    for (int i = 0; i < 5; i++) {
        gemm_kernel<<<gG, 256>>>(x, nullptr,
                                 cnfW + (size_t)i * HH * HH, nullptr,
                                 cnfb + (size_t)i * HH, nullptr,
                                 pp[i & 1], 128, 1);
        x = pp[i & 1];
    }
    head_kernel<<<MB, 256>>>(x, cnfoW, cnfob, out_l, 1);
}

// round 3
// speedup vs baseline: 3.5623x; 1.5723x over previous
#include <cuda_runtime.h>
#include <math.h>

#define NN 100000
#define DD 16
#define HH 128
#define G4 512
#define CC 10
#define PAD 132

// Scratch (no allocations allowed)
__device__ float g_xp[(size_t)NN * G4];   // gate pre-activations: xp = h@Wih^T + b, col=4j+gate
__device__ float g_hA[(size_t)NN * HH];
__device__ float g_hs0[(size_t)NN * HH];
__device__ float g_hs1[(size_t)NN * HH];
__device__ float g_cs[(size_t)NN * HH];

typedef unsigned long long u64;

#define FMA2(d, a, b) \
    asm("fma.rn.f32x2 %0, %1, %2, %3;" : "=l"(d) : "l"(a), "l"(b), "l"(d))
#define PACKDUP(d, f) \
    asm("mov.b64 %0, {%1, %1};" : "=l"(d) : "r"(__float_as_uint(f)))
#define UNPACK2(lo, hi, v) \
    asm("mov.b64 {%0, %1}, %2;" : "=r"(lo), "=r"(hi) : "l"(v))

__device__ __forceinline__ float sigf(float x) {
    return __fdividef(1.f, 1.f + __expf(-x));
}
__device__ __forceinline__ float tanh_(float x) {
    float e = __expf(2.f * x);
    return 1.f - __fdividef(2.f, e + 1.f);
}

// ---------------------------------------------------------------------------
// xp = h @ Wih^T + b, gate-interleaved columns. Block: 128 nodes x 128 cols
// (j-slice of 32), K=128. f32x2 packed math, double-buffered smem.
// Output col (global) = j0*4 + c, weight/bias row r = (c&3)*128 + j0 + (c>>2).
// ---------------------------------------------------------------------------
__global__ __launch_bounds__(256, 2) void xp_gemm_kernel(
    const float* __restrict__ A, const float* __restrict__ Wih,
    const float* __restrict__ bias, float* __restrict__ xp)
{
    __shared__ __align__(16) float As[2][16][PAD];
    __shared__ __align__(16) float Bs[2][16][PAD];

    const int tid = threadIdx.x;
    const int tx = tid & 15, ty = tid >> 4;
    const int m0 = blockIdx.x * 128;
    const int j0 = blockIdx.y * 32;

    int a_m[2], a_k4[2], b_c[2], b_k4[2], b_r[2];
#pragma unroll
    for (int i = 0; i < 2; i++) {
        int idx4 = tid + i * 256;
        a_m[i] = idx4 >> 2; a_k4[i] = idx4 & 3;
        b_c[i] = idx4 >> 2; b_k4[i] = idx4 & 3;
        b_r[i] = (b_c[i] & 3) * HH + j0 + (b_c[i] >> 2);
    }

    float4 ra[2], rb[2];
#pragma unroll
    for (int i = 0; i < 2; i++) {
        int mg = m0 + a_m[i];
        ra[i] = (mg < NN) ? *(const float4*)(A + (size_t)mg * HH + a_k4[i] * 4)
                          : make_float4(0.f, 0.f, 0.f, 0.f);
        rb[i] = *(const float4*)(Wih + (size_t)b_r[i] * HH + b_k4[i] * 4);
    }
#pragma unroll
    for (int i = 0; i < 2; i++) {
        float* pa = &As[0][a_k4[i] * 4][a_m[i]];
        pa[0*PAD] = ra[i].x; pa[1*PAD] = ra[i].y; pa[2*PAD] = ra[i].z; pa[3*PAD] = ra[i].w;
        float* pb = &Bs[0][b_k4[i] * 4][b_c[i]];
        pb[0*PAD] = rb[i].x; pb[1*PAD] = rb[i].y; pb[2*PAD] = rb[i].z; pb[3*PAD] = rb[i].w;
    }
    __syncthreads();

    u64 acc[8][4];
#pragma unroll
    for (int r = 0; r < 8; r++)
#pragma unroll
        for (int c = 0; c < 4; c++) acc[r][c] = 0ull;

    int p = 0;
    for (int it = 0; it < 8; it++) {
        int kn = (it + 1) * 16;
        if (it < 7) {
#pragma unroll
            for (int i = 0; i < 2; i++) {
                int mg = m0 + a_m[i];
                int k = kn + a_k4[i] * 4;
                ra[i] = (mg < NN) ? *(const float4*)(A + (size_t)mg * HH + k)
                                  : make_float4(0.f, 0.f, 0.f, 0.f);
                rb[i] = *(const float4*)(Wih + (size_t)b_r[i] * HH + kn + b_k4[i] * 4);
            }
        }
#pragma unroll
        for (int kl = 0; kl < 16; kl++) {
            const float* arow = &As[p][kl][0];
            const float* brow = &Bs[p][kl][0];
            float4 a0 = *(const float4*)(arow + ty * 8);
            float4 a1 = *(const float4*)(arow + ty * 8 + 4);
            ulonglong2 q0 = *(const ulonglong2*)(brow + tx * 8);
            ulonglong2 q1 = *(const ulonglong2*)(brow + tx * 8 + 4);
            u64 bv[4] = {q0.x, q0.y, q1.x, q1.y};
            float av[8] = {a0.x, a0.y, a0.z, a0.w, a1.x, a1.y, a1.z, a1.w};
            u64 ad[8];
#pragma unroll
            for (int r = 0; r < 8; r++) PACKDUP(ad[r], av[r]);
#pragma unroll
            for (int r = 0; r < 8; r++)
#pragma unroll
                for (int c = 0; c < 4; c++) FMA2(acc[r][c], ad[r], bv[c]);
        }
        if (it < 7) {
            int q = p ^ 1;
#pragma unroll
            for (int i = 0; i < 2; i++) {
                float* pa = &As[q][a_k4[i] * 4][a_m[i]];
                pa[0*PAD] = ra[i].x; pa[1*PAD] = ra[i].y; pa[2*PAD] = ra[i].z; pa[3*PAD] = ra[i].w;
                float* pb = &Bs[q][b_k4[i] * 4][b_c[i]];
                pb[0*PAD] = rb[i].x; pb[1*PAD] = rb[i].y; pb[2*PAD] = rb[i].z; pb[3*PAD] = rb[i].w;
            }
            __syncthreads();
            p = q;
        }
    }

    // bias per column, store
    float bval[8];
#pragma unroll
    for (int cc = 0; cc < 8; cc++) {
        int c = tx * 8 + cc;
        bval[cc] = bias[(c & 3) * HH + j0 + (c >> 2)];
    }
#pragma unroll
    for (int r = 0; r < 8; r++) {
        int mg = m0 + ty * 8 + r;
        if (mg < NN) {
            float v[8];
#pragma unroll
            for (int c = 0; c < 4; c++) {
                unsigned lo, hi;
                UNPACK2(lo, hi, acc[r][c]);
                v[c * 2]     = __uint_as_float(lo) + bval[c * 2];
                v[c * 2 + 1] = __uint_as_float(hi) + bval[c * 2 + 1];
            }
            float* dst = xp + (size_t)mg * G4 + j0 * 4 + tx * 8;
            *(float4*)dst       = make_float4(v[0], v[1], v[2], v[3]);
            *(float4*)(dst + 4) = make_float4(v[4], v[5], v[6], v[7]);
        }
    }
}

// ---------------------------------------------------------------------------
// Step 0: hs = sig(o)*tanh(c), c = sig(i)*tanh(g); gates = gathered xp only.
// One thread per (node, j). NN*HH divisible by 256.
// ---------------------------------------------------------------------------
__global__ __launch_bounds__(256) void lstm_step0_kernel(
    const float* __restrict__ xp, const int* __restrict__ nbr,
    float* __restrict__ hs, float* __restrict__ cs)
{
    int gid = blockIdx.x * 256 + threadIdx.x;
    int m = gid >> 7, j = gid & 127;
    int row = nbr[m * DD];   // step 0 neighbor
    float4 g = *(const float4*)(xp + (size_t)row * G4 + j * 4);
    float cn = sigf(g.x) * tanh_(g.z);
    float hn = sigf(g.w) * tanh_(cn);
    cs[gid] = cn;
    hs[gid] = hn;
}

// ---------------------------------------------------------------------------
// LSTM step t>=1: gates = xp[nbr[m,t]] + hs @ Whh^T (K=128), then pointwise.
// Block: 128 nodes x 32 j (128 gate cols, interleaved c=4*jl+gate).
// xp rows async-gathered into smem at start, added in register epilogue.
// Dynamic smem: As(2*16*132) Bs(2*16*132) XP(128*128) nidx(128) = 99840 B.
// ---------------------------------------------------------------------------
__global__ __launch_bounds__(256, 2) void lstm_step3_kernel(
    const float* __restrict__ xp, const int* __restrict__ nbr, int step,
    const float* __restrict__ hs_in, float* __restrict__ hs_out,
    float* __restrict__ cs, const float* __restrict__ Whh)
{
    extern __shared__ __align__(16) float sm[];
    float* As = sm;                    // [2][16][PAD]
    float* Bs = sm + 2 * 16 * PAD;     // [2][16][PAD]
    float* XP = sm + 4 * 16 * PAD;     // [128][128]
    int* nidx = (int*)(sm + 4 * 16 * PAD + 128 * 128);

    const int tid = threadIdx.x;
    const int tx = tid & 15, ty = tid >> 4;
    const int m0 = blockIdx.x * 128;
    const int j0 = blockIdx.y * 32;

    if (tid < 128) {
        int m = m0 + tid;
        nidx[tid] = (m < NN) ? nbr[m * DD + step] : 0;
    }
    __syncthreads();

    // async gather: 128 xp rows x 128 cols (this block's gate-col slice)
    {
        unsigned xbase = (unsigned)__cvta_generic_to_shared(XP);
#pragma unroll
        for (int i = 0; i < 16; i++) {
            int idx = tid + i * 256;        // 4096 float4 tiles
            int m = idx >> 5, c4 = idx & 31;
            const float* src = xp + (size_t)nidx[m] * G4 + j0 * 4 + c4 * 4;
            unsigned dst = xbase + (unsigned)(m * 128 + c4 * 4) * 4u;
            asm volatile("cp.async.cg.shared.global [%0], [%1], 16;" :: "r"(dst), "l"(src));
        }
        asm volatile("cp.async.commit_group;");
    }

    int a_m[2], a_k4[2], b_c[2], b_k4[2], b_r[2];
#pragma unroll
    for (int i = 0; i < 2; i++) {
        int idx4 = tid + i * 256;
        a_m[i] = idx4 >> 2; a_k4[i] = idx4 & 3;
        b_c[i] = idx4 >> 2; b_k4[i] = idx4 & 3;
        b_r[i] = (b_c[i] & 3) * HH + j0 + (b_c[i] >> 2);
    }

    float4 ra[2], rb[2];
#pragma unroll
    for (int i = 0; i < 2; i++) {
        int mg = m0 + a_m[i];
        ra[i] = (mg < NN) ? *(const float4*)(hs_in + (size_t)mg * HH + a_k4[i] * 4)
                          : make_float4(0.f, 0.f, 0.f, 0.f);
        rb[i] = *(const float4*)(Whh + (size_t)b_r[i] * HH + b_k4[i] * 4);
    }
#pragma unroll
    for (int i = 0; i < 2; i++) {
        float* pa = &As[(a_k4[i] * 4) * PAD + a_m[i]];
        pa[0*PAD] = ra[i].x; pa[1*PAD] = ra[i].y; pa[2*PAD] = ra[i].z; pa[3*PAD] = ra[i].w;
        float* pb = &Bs[(b_k4[i] * 4) * PAD + b_c[i]];
        pb[0*PAD] = rb[i].x; pb[1*PAD] = rb[i].y; pb[2*PAD] = rb[i].z; pb[3*PAD] = rb[i].w;
    }
    __syncthreads();

    u64 acc[8][4];
#pragma unroll
    for (int r = 0; r < 8; r++)
#pragma unroll
        for (int c = 0; c < 4; c++) acc[r][c] = 0ull;

    int p = 0;
    for (int it = 0; it < 8; it++) {
        int kn = (it + 1) * 16;
        if (it < 7) {
#pragma unroll
            for (int i = 0; i < 2; i++) {
                int mg = m0 + a_m[i];
                int k = kn + a_k4[i] * 4;
                ra[i] = (mg < NN) ? *(const float4*)(hs_in + (size_t)mg * HH + k)
                                  : make_float4(0.f, 0.f, 0.f, 0.f);
                rb[i] = *(const float4*)(Whh + (size_t)b_r[i] * HH + kn + b_k4[i] * 4);
            }
        }
        const float* abuf = As + p * 16 * PAD;
        const float* bbuf = Bs + p * 16 * PAD;
#pragma unroll
        for (int kl = 0; kl < 16; kl++) {
            const float* arow = abuf + kl * PAD;
            const float* brow = bbuf + kl * PAD;
            float4 a0 = *(const float4*)(arow + ty * 8);
            float4 a1 = *(const float4*)(arow + ty * 8 + 4);
            ulonglong2 q0 = *(const ulonglong2*)(brow + tx * 8);
            ulonglong2 q1 = *(const ulonglong2*)(brow + tx * 8 + 4);
            u64 bv[4] = {q0.x, q0.y, q1.x, q1.y};
            float av[8] = {a0.x, a0.y, a0.z, a0.w, a1.x, a1.y, a1.z, a1.w};
            u64 ad[8];
#pragma unroll
            for (int r = 0; r < 8; r++) PACKDUP(ad[r], av[r]);
#pragma unroll
            for (int r = 0; r < 8; r++)
#pragma unroll
                for (int c = 0; c < 4; c++) FMA2(acc[r][c], ad[r], bv[c]);
        }
        if (it < 7) {
            int q = p ^ 1;
#pragma unroll
            for (int i = 0; i < 2; i++) {
                float* pa = &As[(q * 16 + a_k4[i] * 4) * PAD + a_m[i]];
                pa[0*PAD] = ra[i].x; pa[1*PAD] = ra[i].y; pa[2*PAD] = ra[i].z; pa[3*PAD] = ra[i].w;
                float* pb = &Bs[(q * 16 + b_k4[i] * 4) * PAD + b_c[i]];
                pb[0*PAD] = rb[i].x; pb[1*PAD] = rb[i].y; pb[2*PAD] = rb[i].z; pb[3*PAD] = rb[i].w;
            }
            __syncthreads();
            p = q;
        }
    }

    // wait for xp gather, then register epilogue
    asm volatile("cp.async.wait_group 0;");
    __syncthreads();

#pragma unroll
    for (int r = 0; r < 8; r++) {
        int ml = ty * 8 + r;
        int mg = m0 + ml;
        if (mg < NN) {
            float4 x0 = *(const float4*)(XP + ml * 128 + tx * 8);
            float4 x1 = *(const float4*)(XP + ml * 128 + tx * 8 + 4);
            float g[8];
            {
                unsigned lo, hi;
                UNPACK2(lo, hi, acc[r][0]); g[0] = __uint_as_float(lo); g[1] = __uint_as_float(hi);
                UNPACK2(lo, hi, acc[r][1]); g[2] = __uint_as_float(lo); g[3] = __uint_as_float(hi);
                UNPACK2(lo, hi, acc[r][2]); g[4] = __uint_as_float(lo); g[5] = __uint_as_float(hi);
                UNPACK2(lo, hi, acc[r][3]); g[6] = __uint_as_float(lo); g[7] = __uint_as_float(hi);
            }
            g[0] += x0.x; g[1] += x0.y; g[2] += x0.z; g[3] += x0.w;
            g[4] += x1.x; g[5] += x1.y; g[6] += x1.z; g[7] += x1.w;

            float2 cold = *(const float2*)(cs + (size_t)mg * HH + j0 + tx * 2);
            float coldv[2] = {cold.x, cold.y};
            float cnv[2], hnv[2];
#pragma unroll
            for (int jj = 0; jj < 2; jj++) {
                float gi = g[jj * 4 + 0];
                float gf = g[jj * 4 + 1];
                float gg = g[jj * 4 + 2];
                float go = g[jj * 4 + 3];
                float cn = sigf(gf) * coldv[jj] + sigf(gi) * tanh_(gg);
                cnv[jj] = cn;
                hnv[jj] = sigf(go) * tanh_(cn);
            }
            *(float2*)(cs + (size_t)mg * HH + j0 + tx * 2)     = make_float2(cnv[0], cnv[1]);
            *(float2*)(hs_out + (size_t)mg * HH + j0 + tx * 2) = make_float2(hnv[0], hnv[1]);
        }
    }
}

// ---------------------------------------------------------------------------
// Generic [N,128] = act( A1@W1^T (+ A2@W2^T) + b1 (+ b2) ), ktot in {128,256}
// ---------------------------------------------------------------------------
__global__ __launch_bounds__(256) void gemm_kernel(
    const float* __restrict__ A1, const float* __restrict__ A2,
    const float* __restrict__ W1, const float* __restrict__ W2,
    const float* __restrict__ b1, const float* __restrict__ b2,
    float* __restrict__ out, int ktot, int relu)
{
    __shared__ __align__(16) float As[16][68];
    __shared__ __align__(16) float Bs[16][132];

    const int tid = threadIdx.x;
    const int tx = tid & 15, ty = tid >> 4;
    const int m0 = blockIdx.x * 64;

    float acc[4][8];
#pragma unroll
    for (int r = 0; r < 4; r++)
#pragma unroll
        for (int c = 0; c < 8; c++) acc[r][c] = 0.f;

    for (int kk = 0; kk < ktot; kk += 16) {
#pragma unroll
        for (int i = 0; i < 4; i++) {
            int idx = tid + i * 256;
            int m = idx >> 4, kl = idx & 15;
            int k = kk + kl;
            int mg = m0 + m;
            float v = 0.f;
            if (mg < NN)
                v = (k < HH) ? A1[(size_t)mg * HH + k] : A2[(size_t)mg * HH + (k - HH)];
            As[kl][m] = v;
        }
#pragma unroll
        for (int i = 0; i < 8; i++) {
            int idx = tid + i * 256;
            int c = idx >> 4, kl = idx & 15;
            int k = kk + kl;
            float w = (k < HH) ? W1[(size_t)c * HH + k] : W2[(size_t)c * HH + (k - HH)];
            Bs[kl][c] = w;
        }
        __syncthreads();
#pragma unroll
        for (int kl = 0; kl < 16; kl++) {
            float4 a  = *(const float4*)&As[kl][ty * 4];
            float4 b0v = *(const float4*)&Bs[kl][tx * 8];
            float4 b1v = *(const float4*)&Bs[kl][tx * 8 + 4];
            float av[4] = {a.x, a.y, a.z, a.w};
            float bv[8] = {b0v.x, b0v.y, b0v.z, b0v.w, b1v.x, b1v.y, b1v.z, b1v.w};
#pragma unroll
            for (int r = 0; r < 4; r++)
#pragma unroll
                for (int c = 0; c < 8; c++)
                    acc[r][c] = fmaf(av[r], bv[c], acc[r][c]);
        }
        __syncthreads();
    }

#pragma unroll
    for (int r = 0; r < 4; r++) {
        int mg = m0 + ty * 4 + r;
        if (mg < NN) {
#pragma unroll
            for (int c = 0; c < 8; c++) {
                int n = tx * 8 + c;
                float v = acc[r][c] + b1[n] + (b2 ? b2[n] : 0.f);
                if (relu) v = fmaxf(v, 0.f);
                acc[r][c] = v;
            }
            *(float4*)&out[(size_t)mg * HH + tx * 8]     = make_float4(acc[r][0], acc[r][1], acc[r][2], acc[r][3]);
            *(float4*)&out[(size_t)mg * HH + tx * 8 + 4] = make_float4(acc[r][4], acc[r][5], acc[r][6], acc[r][7]);
        }
    }
}

// ---------------------------------------------------------------------------
__global__ __launch_bounds__(256) void head_kernel(
    const float* __restrict__ x, const float* __restrict__ W,
    const float* __restrict__ b, float* __restrict__ out, int nout)
{
    __shared__ float xs[64][129];
    __shared__ float ws[CC * HH];
    const int tid = threadIdx.x;
    const int m0 = blockIdx.x * 64;

    for (int i = tid; i < nout * HH; i += 256) ws[i] = W[i];
    for (int i = tid; i < 64 * HH; i += 256) {
        int m = i >> 7, k = i & 127;
        int mg = m0 + m;
        xs[m][k] = (mg < NN) ? x[(size_t)mg * HH + k] : 0.f;
    }
    __syncthreads();

    for (int idx = tid; idx < 64 * nout; idx += 256) {
        int m = idx / nout, c = idx % nout;
        int mg = m0 + m;
        if (mg < NN) {
            float acc = b[c];
#pragma unroll 4
            for (int k = 0; k < HH; k++)
                acc = fmaf(xs[m][k], ws[c * HH + k], acc);
            out[(size_t)mg * nout + c] = acc;
        }
    }
}

// ---------------------------------------------------------------------------
extern "C" void kernel_launch(void* const* d_in, const int* in_sizes, int n_in,
                              void* d_out, int out_size)
{
    const float* h0    = (const float*)d_in[0];
    const int*   nbr   = (const int*)d_in[1];
    const float* Wih   = (const float*)d_in[2];
    const float* Whh   = (const float*)d_in[3];
    const float* lb    = (const float*)d_in[4];
    const float* Wsf   = (const float*)d_in[5];
    const float* bsf   = (const float*)d_in[6];
    const float* Wng   = (const float*)d_in[7];
    const float* bng   = (const float*)d_in[8];
    const float* clsW  = (const float*)d_in[9];
    const float* clsb  = (const float*)d_in[10];
    const float* clsoW = (const float*)d_in[11];
    const float* clsob = (const float*)d_in[12];
    const float* cnfW  = (const float*)d_in[13];
    const float* cnfb  = (const float*)d_in[14];
    const float* cnfoW = (const float*)d_in[15];
    const float* cnfob = (const float*)d_in[16];

    float* out   = (float*)d_out;
    float* out_o = out;                                     // [N, C]
    float* out_h = out + (size_t)NN * CC;                   // [N, H]
    float* out_l = out + (size_t)NN * CC + (size_t)NN * HH; // [N, 1]

    float *xp, *hA, *hs0, *hs1, *cs;
    cudaGetSymbolAddress((void**)&xp,  g_xp);
    cudaGetSymbolAddress((void**)&hA,  g_hA);
    cudaGetSymbolAddress((void**)&hs0, g_hs0);
    cudaGetSymbolAddress((void**)&hs1, g_hs1);
    cudaGetSymbolAddress((void**)&cs,  g_cs);

    const int SMEMB = (4 * 16 * PAD + 128 * 128 + 128) * 4;  // 99840 B
    cudaFuncSetAttribute(lstm_step3_kernel,
                         cudaFuncAttributeMaxDynamicSharedMemorySize, SMEMB);

    const int MBL = (NN + 127) / 128;   // 782
    const int MB  = (NN + 63) / 64;     // 1563
    dim3 gL(MBL, 4);
    dim3 gG(MB, 1);

    const float* hin = h0;
    float* hout_arr[2] = {hA, out_h};

    for (int layer = 0; layer < 2; layer++) {
        const float* Wih_l = Wih + (size_t)layer * 4 * HH * HH;
        const float* Whh_l = Whh + (size_t)layer * 4 * HH * HH;
        const float* lb_l  = lb + (size_t)layer * 4 * HH;

        // 1) precompute gate pre-activations for all nodes
        xp_gemm_kernel<<<gL, 256>>>(hin, Wih_l, lb_l, xp);
        // 2) step 0 (hs=cs=0): pure pointwise on gathered xp
        lstm_step0_kernel<<<(NN * HH) / 256, 256>>>(xp, nbr, hs0, cs);
        // 3) steps 1..15: recurrent Whh GEMM + gathered xp + pointwise
        float* hr = hs0;
        float* hw = hs1;
        for (int t = 1; t < DD; t++) {
            lstm_step3_kernel<<<gL, 256, SMEMB>>>(xp, nbr, t, hr, hw, cs, Whh_l);
            float* tmp = hr; hr = hw; hw = tmp;
        }
        // 4) combine: relu(h@Wself^T + bself + hs@Wneigh^T + bneigh)
        gemm_kernel<<<gG, 256>>>(hin, hr,
                                 Wsf + (size_t)layer * HH * HH,
                                 Wng + (size_t)layer * HH * HH,
                                 bsf + (size_t)layer * HH,
                                 bng + (size_t)layer * HH,
                                 hout_arr[layer], 256, 1);
        hin = hout_arr[layer];
    }

    const float* x = out_h;
    float* pp[2] = {hs0, hs1};
    for (int i = 0; i < 5; i++) {
        gemm_kernel<<<gG, 256>>>(x, nullptr,
                                 clsW + (size_t)i * HH * HH, nullptr,
                                 clsb + (size_t)i * HH, nullptr,
                                 pp[i & 1], 128, 1);
        x = pp[i & 1];
    }
    head_kernel<<<MB, 256>>>(x, clsoW, clsob, out_o, CC);

    x = out_h;
    for (int i = 0; i < 5; i++) {
        gemm_kernel<<<gG, 256>>>(x, nullptr,
                                 cnfW + (size_t)i * HH * HH, nullptr,
                                 cnfb + (size_t)i * HH, nullptr,
                                 pp[i & 1], 128, 1);
        x = pp[i & 1];
    }
    head_kernel<<<MB, 256>>>(x, cnfoW, cnfob, out_l, 1);
}